// round 2
// baseline (speedup 1.0000x reference)
#include <cuda_runtime.h>
#include <math.h>

#define F 256
#define NC 8
#define SC 16
#define NSTEP 4
#define MAXN 200704
#define EMAX 4000000
#define MAXC 65536
#define EPSF 1e-8f

#define OUT_OFF 0
#define SEL_OFF  (NSTEP*NC*SC*NC)            /* 4096 */
#define STEP_OFF (SEL_OFF + NSTEP*NC*SC)     /* 4608 */
#define HX_OFF   (STEP_OFF + NSTEP*NC)       /* 4640 */

// ---------------- device state (no allocation allowed) ----------------
__device__ unsigned int  g_counts[MAXN*2];   // packed u8 counts, 4 classes per u32
__device__ int           g_deg[MAXN];
__device__ int           g_starts[MAXN];
__device__ int           g_cursor[MAXN];
__device__ unsigned char g_entity[MAXN];
__device__ unsigned int  g_cg[MAXN];         // 8-bit class membership mask
__device__ unsigned char g_valid[MAXN];
__device__ int           g_adj[EMAX];        // CSR by dst: src lists
__device__ int           g_cand[MAXC];
__device__ int           g_candCount;
__device__ float         g_candScore[MAXC*NC];
__device__ float         g_inp[NC*F];
__device__ float         g_hx[NC*F];
__device__ float         g_hxden[NC];
__device__ float         g_gi[NC*3*F];
__device__ float         g_gh[NC*3*F];
__device__ int           g_group[NC*SC];     // doubles as last_selected
__device__ int           g_markNode[NC*SC];
__device__ int           g_markClass[NC*SC];
__device__ int           g_markNew[NC*SC];
__device__ int           g_blockSum[512];
__device__ int           g_blockOff[512];

// ---------------- helpers ----------------
__device__ __forceinline__ float blockSum256(float v, float* red) {
    int lane = threadIdx.x & 31, w = threadIdx.x >> 5;
    #pragma unroll
    for (int o = 16; o; o >>= 1) v += __shfl_down_sync(0xffffffffu, v, o);
    if (lane == 0) red[w] = v;
    __syncthreads();
    float r = 0.f;
    if (w == 0) {
        r = (lane < (int)(blockDim.x >> 5)) ? red[lane] : 0.f;
        #pragma unroll
        for (int o = 4; o; o >>= 1) r += __shfl_down_sync(0xffffffffu, r, o);
    }
    __syncthreads();   // red reusable after return; result valid on thread 0
    return r;
}

// ---------------- init ----------------
__global__ void k_zero(int n) {
    int i = blockIdx.x * blockDim.x + threadIdx.x;
    if (i < 2 * n) g_counts[i] = 0u;
    if (i < n) { g_deg[i] = 0; g_entity[i] = 0; g_cg[i] = 0u; }
    if (i < NC * F) g_hx[i] = 0.f;
}

__global__ void k_seed(const int* __restrict__ seeds) {
    int i = threadIdx.x;
    if (i < NC * SC) {
        int s = seeds[i];
        g_entity[s] = 1;
        atomicOr(&g_cg[s], 1u << (i / SC));
        g_group[i] = s;
        g_markNode[i] = s;
        g_markClass[i] = i / SC;
        g_markNew[i] = 1;
    }
}

// ---------------- CSR build ----------------
__global__ void k_hist(const int* __restrict__ dst, int E) {
    int i = blockIdx.x * blockDim.x + threadIdx.x;
    int e4 = E >> 2;
    const int4* d4 = (const int4*)dst;
    for (int j = i; j < e4; j += gridDim.x * blockDim.x) {
        int4 v = d4[j];
        atomicAdd(&g_deg[v.x], 1); atomicAdd(&g_deg[v.y], 1);
        atomicAdd(&g_deg[v.z], 1); atomicAdd(&g_deg[v.w], 1);
    }
    if (i == 0) for (int e = e4 << 2; e < E; ++e) atomicAdd(&g_deg[dst[e]], 1);
}

__global__ void k_scan1(int n) {
    __shared__ int sh[1024];
    int t = threadIdx.x, i = blockIdx.x * 1024 + t;
    int x = (i < n) ? g_deg[i] : 0;
    sh[t] = x; __syncthreads();
    for (int off = 1; off < 1024; off <<= 1) {
        int a = (t >= off) ? sh[t - off] : 0;
        __syncthreads();
        sh[t] += a;
        __syncthreads();
    }
    if (i < n) g_starts[i] = sh[t] - x;
    if (t == 1023) g_blockSum[blockIdx.x] = sh[1023];
}

__global__ void k_scan2(int nb) {
    if (threadIdx.x == 0) {
        int run = 0;
        for (int b = 0; b < nb; b++) { g_blockOff[b] = run; run += g_blockSum[b]; }
    }
}

__global__ void k_scan3(int n) {
    int t = threadIdx.x, i = blockIdx.x * 1024 + t;
    if (i < n) {
        int v = g_starts[i] + g_blockOff[blockIdx.x];
        g_starts[i] = v;
        g_cursor[i] = v;
    }
}

__global__ void k_scatter(const int* __restrict__ src, const int* __restrict__ dst, int E) {
    int i = blockIdx.x * blockDim.x + threadIdx.x;
    int e4 = E >> 2;
    const int4* s4 = (const int4*)src;
    const int4* d4 = (const int4*)dst;
    for (int j = i; j < e4; j += gridDim.x * blockDim.x) {
        int4 d = d4[j]; int4 s = s4[j];
        int p;
        p = atomicAdd(&g_cursor[d.x], 1); g_adj[p] = s.x;
        p = atomicAdd(&g_cursor[d.y], 1); g_adj[p] = s.y;
        p = atomicAdd(&g_cursor[d.z], 1); g_adj[p] = s.z;
        p = atomicAdd(&g_cursor[d.w], 1); g_adj[p] = s.w;
    }
    if (i == 0) for (int e = e4 << 2; e < E; ++e) {
        int p = atomicAdd(&g_cursor[dst[e]], 1); g_adj[p] = src[e];
    }
}

// incremental counts: walk in-edges of newly marked (node,class) pairs
__global__ void k_apply() {
    int p = blockIdx.x;
    if (!g_markNew[p]) return;
    int j = g_markNode[p], c = g_markClass[p];
    int st = g_starts[j], d = g_deg[j];
    unsigned inc = 1u << ((c & 3) * 8);
    int w = c >> 2;
    for (int e = threadIdx.x; e < d; e += blockDim.x) {
        int s = g_adj[st + e];
        atomicAdd(&g_counts[(size_t)s * 2 + w], inc);
    }
}

// ---------------- per-step compute ----------------
__global__ void k_pool(const float* __restrict__ es) {
    int c = blockIdx.x, t = threadIdx.x;
    float s = 0.f;
    #pragma unroll
    for (int j = 0; j < SC; j++)
        s += es[(size_t)g_group[c * SC + j] * F + t];
    g_inp[c * F + t] = s * (1.0f / SC);
}

__global__ void k_gemm(const float* __restrict__ W_ih, const float* __restrict__ W_hh) {
    __shared__ float shv[2 * NC * F];  // 16KB: [inp(8x256), hx(8x256)]
    int t = threadIdx.x;
    for (int i = t; i < NC * F; i += 256) {
        shv[i] = g_inp[i];
        shv[NC * F + i] = g_hx[i];
    }
    __syncthreads();
    int warp = (blockIdx.x * blockDim.x + t) >> 5;
    int lane = t & 31;
    int totalW = gridDim.x * (blockDim.x >> 5);
    for (int job = warp; job < 2 * 3 * F; job += totalW) {
        int m = (job >= 3 * F) ? 1 : 0;
        int r = job - m * 3 * F;
        const float* Wr = (m ? W_hh : W_ih) + (size_t)r * F;
        const float4* w4 = (const float4*)Wr;
        float4 a = w4[lane * 2], b = w4[lane * 2 + 1];
        float wv[8] = {a.x, a.y, a.z, a.w, b.x, b.y, b.z, b.w};
        const float* vecb = shv + m * NC * F;
        #pragma unroll
        for (int c = 0; c < NC; c++) {
            const float* v = vecb + c * F + lane * 8;
            float d = wv[0]*v[0] + wv[1]*v[1] + wv[2]*v[2] + wv[3]*v[3]
                    + wv[4]*v[4] + wv[5]*v[5] + wv[6]*v[6] + wv[7]*v[7];
            #pragma unroll
            for (int o = 16; o; o >>= 1) d += __shfl_down_sync(0xffffffffu, d, o);
            if (lane == 0) { (m ? g_gh : g_gi)[c * 3 * F + r] = d; }
        }
    }
}

__global__ void k_gate(const float* __restrict__ b_ih, const float* __restrict__ b_hh,
                       float* __restrict__ out, int step) {
    __shared__ float red[8];
    int c = blockIdx.x, k = threadIdx.x;
    float gir = g_gi[c*3*F + k]         + b_ih[k];
    float giz = g_gi[c*3*F + F + k]     + b_ih[F + k];
    float gin = g_gi[c*3*F + 2*F + k]   + b_ih[2*F + k];
    float ghr = g_gh[c*3*F + k]         + b_hh[k];
    float ghz = g_gh[c*3*F + F + k]     + b_hh[F + k];
    float ghn = g_gh[c*3*F + 2*F + k]   + b_hh[2*F + k];
    float r = 1.f / (1.f + expf(-(gir + ghr)));
    float z = 1.f / (1.f + expf(-(giz + ghz)));
    float nn = tanhf(gin + r * ghn);
    float h = (1.f - z) * nn + z * g_hx[c * F + k];
    g_hx[c * F + k] = h;
    out[HX_OFF + step * NC * F + c * F + k] = h;
    float s2 = blockSum256(h * h, red);
    if (k == 0) g_hxden[c] = sqrtf(s2) + EPSF;
    if (c == 0 && k == 0) g_candCount = 0;
}

__global__ void k_valid(int n, int mm) {
    int i = blockIdx.x * blockDim.x + threadIdx.x;
    if (i >= n) return;
    unsigned vm = 0;
    if (!g_entity[i]) {
        unsigned u0 = g_counts[2 * i], u1 = g_counts[2 * i + 1];
        #pragma unroll
        for (int c = 0; c < 4; c++)
            if (((u0 >> (c * 8)) & 0xffu) >= (unsigned)mm) vm |= 1u << c;
        #pragma unroll
        for (int c = 0; c < 4; c++)
            if (((u1 >> (c * 8)) & 0xffu) >= (unsigned)mm) vm |= 1u << (c + 4);
    }
    g_valid[i] = (unsigned char)vm;
    if (vm) {
        int p = atomicAdd(&g_candCount, 1);
        if (p < MAXC) g_cand[p] = i;
    }
}

__global__ void k_score(const float* __restrict__ es) {
    __shared__ float red[8];
    int cc = g_candCount; if (cc > MAXC) cc = MAXC;
    int t = threadIdx.x;
    for (int ci = blockIdx.x; ci < cc; ci += gridDim.x) {
        int node = g_cand[ci];
        float x = es[(size_t)node * F + t];
        float n2 = blockSum256(x * x, red);
        float den = sqrtf(n2) + EPSF;  // valid on t0
        #pragma unroll
        for (int c = 0; c < NC; c++) {
            float d = blockSum256(x * g_hx[c * F + t], red);
            if (t == 0)
                g_candScore[ci * NC + c] = 0.5f * (d / (den * g_hxden[c])) + 0.5f;
        }
    }
}

// per-class top-16 replicating jax.lax.top_k semantics (score desc, index asc,
// -1 fill => smallest indices not valid-for-this-class)
__global__ void k_select(float* __restrict__ out, int step) {
    __shared__ unsigned ch[MAXC / 32];
    __shared__ unsigned long long red[256];
    int c = blockIdx.x, t = threadIdx.x;
    int cc = g_candCount; if (cc > MAXC) cc = MAXC;
    for (int i = t; i < MAXC / 32; i += 256) ch[i] = 0u;
    __syncthreads();
    int slot = 0;
    for (; slot < SC; ++slot) {
        unsigned long long best = 0ull;
        for (int j = t; j < cc; j += 256) {
            int nd = g_cand[j];
            if (((g_valid[nd] >> c) & 1u) && !((ch[j >> 5] >> (j & 31)) & 1u)) {
                float sc = g_candScore[j * NC + c];
                unsigned u = __float_as_uint(sc);
                u ^= (u & 0x80000000u) ? 0xffffffffu : 0x80000000u;
                unsigned long long k = (((unsigned long long)u) << 32)
                                     | (unsigned long long)(0xffffffffu - (unsigned)nd);
                if (k > best) best = k;
            }
        }
        red[t] = best; __syncthreads();
        for (int s = 128; s; s >>= 1) {
            if (t < s && red[t + s] > red[t]) red[t] = red[t + s];
            __syncthreads();
        }
        unsigned long long bk = red[0];
        __syncthreads();
        if (bk == 0ull) break;
        int node = (int)(0xffffffffu - (unsigned)(bk & 0xffffffffu));
        for (int j = t; j < cc; j += 256)
            if (g_cand[j] == node) ch[j >> 5] |= (1u << (j & 31));
        if (t == 0) {
            g_group[c * SC + slot] = node;
            out[SEL_OFF + step * NC * SC + c * SC + slot] = (float)node;
        }
        __syncthreads();
    }
    if (t == 0) {
        int p = 0;
        for (; slot < SC; ++slot) {
            while ((g_valid[p] >> c) & 1u) ++p;
            g_group[c * SC + slot] = p;
            out[SEL_OFF + step * NC * SC + c * SC + slot] = (float)p;
            ++p;
        }
        out[STEP_OFF + step * NC + c] = 16.0f;
    }
}

__global__ void k_finalize(const float* __restrict__ es, float* __restrict__ out, int step) {
    __shared__ float red[8];
    int s = blockIdx.x, t = threadIdx.x;
    int c = s / SC;
    int node = g_group[s];
    if (t == 0) {
        unsigned old = atomicOr(&g_cg[node], 1u << c);
        g_entity[node] = 1;
        g_markNode[s] = node;
        g_markClass[s] = c;
        g_markNew[s] = ((old >> c) & 1u) ? 0 : 1;
    }
    unsigned vm = g_valid[node];            // uniform across block
    float* orow = out + OUT_OFF + step * (NC * SC * NC) + s * NC;
    if (vm == 0u) {
        if (t < NC) orow[t] = 0.f;
        return;
    }
    float x = es[(size_t)node * F + t];
    float n2 = blockSum256(x * x, red);
    float den = sqrtf(n2) + EPSF;           // valid on t0
    #pragma unroll
    for (int c2 = 0; c2 < NC; c2++) {
        float d = blockSum256(x * g_hx[c2 * F + t], red);
        if (t == 0) orow[c2] = 0.5f * (d / (den * g_hxden[c2])) + 0.5f;
    }
}

// ---------------- launch ----------------
extern "C" void kernel_launch(void* const* d_in, const int* in_sizes, int n_in,
                              void* d_out, int out_size) {
    const int*   seeds = (const int*)d_in[0];
    const int*   esrc  = (const int*)d_in[1];
    const int*   edst  = (const int*)d_in[2];
    const float* es    = (const float*)d_in[3];
    const float* W_ih  = (const float*)d_in[4];
    const float* W_hh  = (const float*)d_in[5];
    const float* b_ih  = (const float*)d_in[6];
    const float* b_hh  = (const float*)d_in[7];
    float* out = (float*)d_out;
    int E = in_sizes[1];
    int n = in_sizes[3] / F;
    int nb = (n + 1023) / 1024;

    k_zero<<<(2 * n + 255) / 256, 256>>>(n);
    k_seed<<<1, 128>>>(seeds);
    k_hist<<<2048, 256>>>(edst, E);
    k_scan1<<<nb, 1024>>>(n);
    k_scan2<<<1, 32>>>(nb);
    k_scan3<<<nb, 1024>>>(n);
    k_scatter<<<2048, 256>>>(esrc, edst, E);
    k_apply<<<NC * SC, 128>>>();

    const int mms[NSTEP] = {3, 2, 2, 2};
    for (int step = 0; step < NSTEP; step++) {
        k_pool<<<NC, F>>>(es);
        k_gemm<<<96, 256>>>(W_ih, W_hh);
        k_gate<<<NC, F>>>(b_ih, b_hh, out, step);
        k_valid<<<(n + 255) / 256, 256>>>(n, mms[step]);
        k_score<<<512, 256>>>(es);
        k_select<<<NC, 256>>>(out, step);
        k_finalize<<<NC * SC, 256>>>(es, out, step);
        k_apply<<<NC * SC, 128>>>();
    }
}

// round 3
// speedup vs baseline: 1.2893x; 1.2893x over previous
#include <cuda_runtime.h>
#include <math.h>

#define F 256
#define NC 8
#define SC 16
#define NSTEP 4
#define MAXN 200704
#define BMPW (MAXN/32)
#define CANDCAP 4096
#define EPSF 1e-8f
#define NT 256

#define OUT_OFF 0
#define SEL_OFF  (NSTEP*NC*SC*NC)            /* 4096 */
#define STEP_OFF (SEL_OFF + NSTEP*NC*SC)     /* 4608 */
#define HX_OFF   (STEP_OFF + NSTEP*NC)       /* 4640 */

// ---------------- device state ----------------
__device__ unsigned       g_counts[MAXN*2];   // packed u8 counts, 4 classes/u32
__device__ unsigned char  g_entity[MAXN];
__device__ unsigned       g_cg[MAXN];         // class membership mask
__device__ unsigned       g_newMask[MAXN];    // newly marked class bits
__device__ unsigned       g_bitmap[BMPW];     // "has new mark" bit per node
__device__ unsigned char  g_valid[MAXN];
__device__ int            g_cand[CANDCAP];
__device__ int            g_candCount;
__device__ float          g_candScore[CANDCAP*NC];
__device__ float          g_inp[NC*F];
__device__ float          g_hx[NC*F];
__device__ float          g_hxden[NC];
__device__ float          g_gi[NC*3*F];
__device__ float          g_gh[NC*3*F];
__device__ int            g_group[NC*SC];
__device__ int            g_markNode[NC*SC];
__device__ unsigned       g_barArrive;
__device__ unsigned       g_barGen;

union SH {
    float    shv[2*NC*F];                               // 16KB (gemm)
    unsigned bmp[BMPW];                                  // 25KB (edge scan)
    struct { unsigned long long red[NT]; unsigned ch[CANDCAP/32]; } sel;
};

// ---------------- grid barrier (reset-free, replay-safe) ----------------
__device__ __forceinline__ void gsync(unsigned barBase, unsigned &nbar, int NB) {
    __syncthreads();
    if (threadIdx.x == 0) {
        __threadfence();
        unsigned target = barBase + nbar + 1u;
        unsigned t = atomicAdd(&g_barArrive, 1u);
        if (t == target * (unsigned)NB - 1u) {
            *(volatile unsigned*)&g_barGen = target;       // release
        } else {
            while (*(volatile unsigned*)&g_barGen - barBase < nbar + 1u)
                __nanosleep(32);
        }
        __threadfence();                                    // acquire
    }
    __syncthreads();
    nbar++;
}

__device__ __forceinline__ float blockSum256(float v, float* red) {
    int lane = threadIdx.x & 31, w = threadIdx.x >> 5;
    #pragma unroll
    for (int o = 16; o; o >>= 1) v += __shfl_down_sync(0xffffffffu, v, o);
    if (lane == 0) red[w] = v;
    __syncthreads();
    float r = 0.f;
    if (w == 0) {
        r = (lane < 8) ? red[lane] : 0.f;
        #pragma unroll
        for (int o = 4; o; o >>= 1) r += __shfl_down_sync(0xffffffffu, r, o);
    }
    __syncthreads();
    return r;   // valid on thread 0
}

__device__ __forceinline__ void applyOne(int src, int dst) {
    unsigned m = g_newMask[dst];
    while (m) {
        int c = __ffs(m) - 1; m &= m - 1;
        atomicAdd(&g_counts[(size_t)src * 2 + (c >> 2)], 1u << ((c & 3) * 8));
    }
}

// streaming edge scan: counts[src] += new marks on dst
__device__ void edgeScan(SH& sh, const int* __restrict__ esrc,
                         const int* __restrict__ edst, int E, int gid, int GT) {
    for (int i = threadIdx.x; i < BMPW; i += NT) sh.bmp[i] = g_bitmap[i];
    __syncthreads();
    int e4 = E >> 2;
    const int4* d4 = (const int4*)edst;
    const int4* s4 = (const int4*)esrc;
    for (int j = gid; j < e4; j += GT) {
        int4 d = d4[j];
        unsigned h0 = (sh.bmp[(unsigned)d.x >> 5] >> (d.x & 31)) & 1u;
        unsigned h1 = (sh.bmp[(unsigned)d.y >> 5] >> (d.y & 31)) & 1u;
        unsigned h2 = (sh.bmp[(unsigned)d.z >> 5] >> (d.z & 31)) & 1u;
        unsigned h3 = (sh.bmp[(unsigned)d.w >> 5] >> (d.w & 31)) & 1u;
        if (h0 | h1 | h2 | h3) {
            int4 s = s4[j];
            if (h0) applyOne(s.x, d.x);
            if (h1) applyOne(s.y, d.y);
            if (h2) applyOne(s.z, d.z);
            if (h3) applyOne(s.w, d.w);
        }
    }
    if (gid == 0) {
        for (int e = e4 << 2; e < E; ++e) {
            int d = edst[e];
            if ((g_bitmap[(unsigned)d >> 5] >> (d & 31)) & 1u) applyOne(esrc[e], d);
        }
    }
}

__device__ void poolClass(const float* __restrict__ es, int c) {
    int t = threadIdx.x;
    float s = 0.f;
    #pragma unroll
    for (int j = 0; j < SC; j++)
        s += es[(size_t)g_group[c * SC + j] * F + t];
    g_inp[c * F + t] = s * (1.0f / SC);
}

__global__ __launch_bounds__(NT, 1) void fused_kernel(
    const int* __restrict__ seeds, const int* __restrict__ esrc,
    const int* __restrict__ edst, const float* __restrict__ es,
    const float* __restrict__ W_ih, const float* __restrict__ W_hh,
    const float* __restrict__ b_ih, const float* __restrict__ b_hh,
    float* __restrict__ out, int E, int n)
{
    __shared__ SH sh;
    __shared__ float redsm[8];
    __shared__ unsigned sBase;
    const int NB = gridDim.x;
    const int tid = threadIdx.x, bid = blockIdx.x;
    const int gid = bid * NT + tid, GT = NB * NT;

    if (tid == 0) sBase = *(volatile unsigned*)&g_barGen;
    __syncthreads();
    const unsigned barBase = sBase;
    unsigned nbar = 0;

    // ---- P0: zero state ----
    for (int i = gid; i < 2 * n; i += GT) g_counts[i] = 0u;
    for (int i = gid; i < n; i += GT) {
        g_entity[i] = 0; g_cg[i] = 0u; g_newMask[i] = 0u;
    }
    for (int i = gid; i < BMPW; i += GT) g_bitmap[i] = 0u;
    for (int i = gid; i < NC * F; i += GT) g_hx[i] = 0.f;
    if (gid == 0) g_candCount = 0;
    gsync(barBase, nbar, NB);

    // ---- P1: seed marks ----
    if (bid == 0 && tid < NC * SC) {
        int s = seeds[tid], c = tid >> 4;
        g_entity[s] = 1;
        atomicOr(&g_cg[s], 1u << c);
        atomicOr(&g_newMask[s], 1u << c);
        atomicOr(&g_bitmap[(unsigned)s >> 5], 1u << (s & 31));
        g_group[tid] = s;
        g_markNode[tid] = s;
    }
    gsync(barBase, nbar, NB);

    // ---- P2: initial apply (seeds) + pool ----
    if (bid < NC) poolClass(es, bid);
    edgeScan(sh, esrc, edst, E, gid, GT);
    gsync(barBase, nbar, NB);

    for (int step = 0; step < NSTEP; step++) {
        int mm = (step == 0) ? 3 : 2;

        // ---- gemm (+ clears for this step's new marks) ----
        for (int i = gid; i < BMPW; i += GT) g_bitmap[i] = 0u;
        if (bid == 1 && tid < NC * SC) g_newMask[g_markNode[tid]] = 0u;
        if (gid == 2 * NT) g_candCount = 0;
        for (int i = tid; i < NC * F; i += NT) {
            sh.shv[i] = g_inp[i];
            sh.shv[NC * F + i] = g_hx[i];
        }
        __syncthreads();
        {
            int warp = (bid * NT + tid) >> 5, lane = tid & 31;
            int totalW = NB * (NT >> 5);
            for (int job = warp; job < 2 * 3 * F; job += totalW) {
                int m = (job >= 3 * F) ? 1 : 0;
                int r = job - m * 3 * F;
                const float4* w4 = (const float4*)((m ? W_hh : W_ih) + (size_t)r * F);
                float4 a = w4[lane * 2], b = w4[lane * 2 + 1];
                float wv[8] = {a.x, a.y, a.z, a.w, b.x, b.y, b.z, b.w};
                const float* vecb = sh.shv + m * NC * F;
                #pragma unroll
                for (int c = 0; c < NC; c++) {
                    const float* v = vecb + c * F + lane * 8;
                    float d = wv[0]*v[0] + wv[1]*v[1] + wv[2]*v[2] + wv[3]*v[3]
                            + wv[4]*v[4] + wv[5]*v[5] + wv[6]*v[6] + wv[7]*v[7];
                    #pragma unroll
                    for (int o = 16; o; o >>= 1) d += __shfl_down_sync(0xffffffffu, d, o);
                    if (lane == 0) (m ? g_gh : g_gi)[c * 3 * F + r] = d;
                }
            }
        }
        gsync(barBase, nbar, NB);

        // ---- gate (blocks 0-7) || valid scan (blocks 8+) ----
        if (bid < NC) {
            int c = bid, k = tid;
            float gir = g_gi[c*3*F + k]       + b_ih[k];
            float giz = g_gi[c*3*F + F + k]   + b_ih[F + k];
            float gin = g_gi[c*3*F + 2*F + k] + b_ih[2*F + k];
            float ghr = g_gh[c*3*F + k]       + b_hh[k];
            float ghz = g_gh[c*3*F + F + k]   + b_hh[F + k];
            float ghn = g_gh[c*3*F + 2*F + k] + b_hh[2*F + k];
            float r = 1.f / (1.f + expf(-(gir + ghr)));
            float z = 1.f / (1.f + expf(-(giz + ghz)));
            float nn = tanhf(gin + r * ghn);
            float h = (1.f - z) * nn + z * g_hx[c * F + k];
            g_hx[c * F + k] = h;
            out[HX_OFF + step * NC * F + c * F + k] = h;
            float s2 = blockSum256(h * h, redsm);
            if (k == 0) g_hxden[c] = sqrtf(s2) + EPSF;
        } else {
            int start = (bid - NC) * NT + tid, stride = (NB - NC) * NT;
            for (int i = start; i < n; i += stride) {
                unsigned vm = 0;
                if (!g_entity[i]) {
                    uint2 u = *(const uint2*)&g_counts[(size_t)i * 2];
                    #pragma unroll
                    for (int c = 0; c < 4; c++)
                        if (((u.x >> (c * 8)) & 0xffu) >= (unsigned)mm) vm |= 1u << c;
                    #pragma unroll
                    for (int c = 0; c < 4; c++)
                        if (((u.y >> (c * 8)) & 0xffu) >= (unsigned)mm) vm |= 1u << (c + 4);
                }
                g_valid[i] = (unsigned char)vm;
                if (vm) {
                    int p = atomicAdd(&g_candCount, 1);
                    if (p < CANDCAP) g_cand[p] = i;
                }
            }
        }
        gsync(barBase, nbar, NB);

        // ---- score candidates ----
        {
            int cc = g_candCount; if (cc > CANDCAP) cc = CANDCAP;
            for (int ci = bid; ci < cc; ci += NB) {
                int node = g_cand[ci];
                float x = es[(size_t)node * F + tid];
                float n2 = blockSum256(x * x, redsm);
                float den = sqrtf(n2) + EPSF;     // thread 0
                #pragma unroll
                for (int c = 0; c < NC; c++) {
                    float d = blockSum256(x * g_hx[c * F + tid], redsm);
                    if (tid == 0)
                        g_candScore[ci * NC + c] = 0.5f * (d / (den * g_hxden[c])) + 0.5f;
                }
            }
        }
        gsync(barBase, nbar, NB);

        // ---- select: per-class top-16 (top_k semantics) ----
        if (bid < NC) {
            int c = bid;
            int cc = g_candCount; if (cc > CANDCAP) cc = CANDCAP;
            for (int i = tid; i < CANDCAP / 32; i += NT) sh.sel.ch[i] = 0u;
            __syncthreads();
            int slot = 0;
            for (; slot < SC; ++slot) {
                unsigned long long best = 0ull;
                for (int j = tid; j < cc; j += NT) {
                    int nd = g_cand[j];
                    if (((g_valid[nd] >> c) & 1u) && !((sh.sel.ch[j >> 5] >> (j & 31)) & 1u)) {
                        unsigned u = __float_as_uint(g_candScore[j * NC + c]);
                        u ^= (u & 0x80000000u) ? 0xffffffffu : 0x80000000u;
                        unsigned long long k = (((unsigned long long)u) << 32)
                                             | (unsigned long long)(0xffffffffu - (unsigned)nd);
                        if (k > best) best = k;
                    }
                }
                sh.sel.red[tid] = best; __syncthreads();
                for (int s = 128; s; s >>= 1) {
                    if (tid < s && sh.sel.red[tid + s] > sh.sel.red[tid])
                        sh.sel.red[tid] = sh.sel.red[tid + s];
                    __syncthreads();
                }
                unsigned long long bk = sh.sel.red[0];
                __syncthreads();
                if (bk == 0ull) break;
                int node = (int)(0xffffffffu - (unsigned)(bk & 0xffffffffu));
                for (int j = tid; j < cc; j += NT)
                    if (g_cand[j] == node) sh.sel.ch[j >> 5] |= (1u << (j & 31));
                if (tid == 0) {
                    g_group[c * SC + slot] = node;
                    out[SEL_OFF + step * NC * SC + c * SC + slot] = (float)node;
                }
                __syncthreads();
            }
            if (tid == 0) {
                int p = 0;
                for (; slot < SC; ++slot) {
                    while ((g_valid[p] >> c) & 1u) ++p;
                    g_group[c * SC + slot] = p;
                    out[SEL_OFF + step * NC * SC + c * SC + slot] = (float)p;
                    ++p;
                }
                out[STEP_OFF + step * NC + c] = 16.0f;
            }
        }
        gsync(barBase, nbar, NB);

        // ---- finalize: marks + output rows (+ pool for next step) ----
        if (bid < NC * SC) {
            int slot = bid, c = slot / SC;
            int node = g_group[slot];
            if (tid == 0) {
                unsigned old = atomicOr(&g_cg[node], 1u << c);
                g_entity[node] = 1;
                g_markNode[slot] = node;
                if (!((old >> c) & 1u)) {
                    atomicOr(&g_newMask[node], 1u << c);
                    atomicOr(&g_bitmap[(unsigned)node >> 5], 1u << (node & 31));
                }
            }
            unsigned vm = g_valid[node];
            float* orow = out + OUT_OFF + step * (NC * SC * NC) + slot * NC;
            if (vm == 0u) {
                if (tid < NC) orow[tid] = 0.f;
            } else {
                float x = es[(size_t)node * F + tid];
                float n2 = blockSum256(x * x, redsm);
                float den = sqrtf(n2) + EPSF;
                #pragma unroll
                for (int c2 = 0; c2 < NC; c2++) {
                    float d = blockSum256(x * g_hx[c2 * F + tid], redsm);
                    if (tid == 0) orow[c2] = 0.5f * (d / (den * g_hxden[c2])) + 0.5f;
                }
            }
        }
        if (bid < NC && step < NSTEP - 1) poolClass(es, bid);
        gsync(barBase, nbar, NB);

        // ---- apply new marks (not needed after the last step) ----
        if (step < NSTEP - 1) {
            edgeScan(sh, esrc, edst, E, gid, GT);
            gsync(barBase, nbar, NB);
        }
    }
}

// ---------------- launch ----------------
extern "C" void kernel_launch(void* const* d_in, const int* in_sizes, int n_in,
                              void* d_out, int out_size) {
    const int*   seeds = (const int*)d_in[0];
    const int*   esrc  = (const int*)d_in[1];
    const int*   edst  = (const int*)d_in[2];
    const float* es    = (const float*)d_in[3];
    const float* W_ih  = (const float*)d_in[4];
    const float* W_hh  = (const float*)d_in[5];
    const float* b_ih  = (const float*)d_in[6];
    const float* b_hh  = (const float*)d_in[7];
    float* out = (float*)d_out;
    int E = in_sizes[1];
    int n = in_sizes[3] / F;

    int dev = 0, nsm = 0;
    cudaGetDevice(&dev);
    cudaDeviceGetAttribute(&nsm, cudaDevAttrMultiProcessorCount, dev);
    if (nsm <= 0 || nsm > 512) nsm = 148;

    fused_kernel<<<nsm, NT>>>(seeds, esrc, edst, es, W_ih, W_hh, b_ih, b_hh, out, E, n);
}

// round 4
// speedup vs baseline: 1.7886x; 1.3873x over previous
#include <cuda_runtime.h>
#include <math.h>

#define F 256
#define NC 8
#define SC 16
#define NSTEP 4
#define MAXN 200704
#define BMPW (MAXN/32)
#define CANDCAP 4096
#define EPSF 1e-8f
#define NT 512
#define NWARP (NT/32)
#define GEMMB 16

#define OUT_OFF 0
#define SEL_OFF  (NSTEP*NC*SC*NC)            /* 4096 */
#define STEP_OFF (SEL_OFF + NSTEP*NC*SC)     /* 4608 */
#define HX_OFF   (STEP_OFF + NSTEP*NC)       /* 4640 */

// ---------------- device state ----------------
__device__ unsigned       g_counts[MAXN*2];   // packed u8 counts, 4 classes/u32
__device__ unsigned char  g_entity[MAXN];
__device__ unsigned       g_cg[MAXN];         // class membership mask
__device__ unsigned       g_newMask[MAXN];    // newly marked class bits
__device__ unsigned       g_bitmap[BMPW];     // "has new mark" bit per node
__device__ unsigned char  g_valid[MAXN];
__device__ int            g_cand[CANDCAP];
__device__ int            g_candCount;
__device__ float          g_candScore[CANDCAP*NC];
__device__ float          g_inp[NC*F];
__device__ float          g_hx[NC*F];
__device__ float          g_hxden[NC];
__device__ float          g_gi[NC*3*F];
__device__ float          g_gh[NC*3*F];
__device__ int            g_markNode[NC*SC];
__device__ unsigned       g_barArrive;
__device__ unsigned       g_barGen;

union SH {
    float    shv[2*NC*F];                    // 16KB (gemm)
    unsigned bmp[BMPW];                      // 25KB (edge scan)
    float    hxsc[NC*F];                     // 8KB  (score)
    struct {                                 // select+finalize
        float hxs[NC*F];                     // 8KB
        unsigned long long red[NWARP];
        unsigned long long bestk;
        unsigned ch[CANDCAP/32];
        int snode[SC];
    } sel;
};

// ---------------- grid barrier (reset-free, replay-safe) ----------------
__device__ __forceinline__ void gsync(unsigned barBase, unsigned &nbar, int NB) {
    __syncthreads();
    if (threadIdx.x == 0) {
        __threadfence();
        unsigned target = barBase + nbar + 1u;
        unsigned t = atomicAdd(&g_barArrive, 1u);
        if (t == target * (unsigned)NB - 1u) {
            *(volatile unsigned*)&g_barGen = target;       // release
        } else {
            while (*(volatile unsigned*)&g_barGen - barBase < nbar + 1u)
                __nanosleep(32);
        }
        __threadfence();                                    // acquire
    }
    __syncthreads();
    nbar++;
}

// all threads participate; inactive contribute 0; result valid on thread 0
__device__ __forceinline__ float blockSumAll(float v, float* red) {
    int lane = threadIdx.x & 31, w = threadIdx.x >> 5;
    #pragma unroll
    for (int o = 16; o; o >>= 1) v += __shfl_down_sync(0xffffffffu, v, o);
    if (lane == 0) red[w] = v;
    __syncthreads();
    float r = 0.f;
    if (w == 0) {
        r = (lane < NWARP) ? red[lane] : 0.f;
        #pragma unroll
        for (int o = 8; o; o >>= 1) r += __shfl_down_sync(0xffffffffu, r, o);
    }
    __syncthreads();
    return r;
}

__device__ __forceinline__ void applyOne(int src, int dst) {
    unsigned m = g_newMask[dst];
    while (m) {
        int c = __ffs(m) - 1; m &= m - 1;
        atomicAdd(&g_counts[(size_t)src * 2 + (c >> 2)], 1u << ((c & 3) * 8));
    }
}

// streaming edge scan over scan blocks [GEMMB, NB)
__device__ void edgeScan(SH& sh, const int* __restrict__ esrc,
                         const int* __restrict__ edst, int E, int bid, int NB) {
    for (int i = threadIdx.x; i < BMPW; i += NT) sh.bmp[i] = g_bitmap[i];
    __syncthreads();
    int sid = (bid - GEMMB) * NT + threadIdx.x;
    int ST  = (NB - GEMMB) * NT;
    int e4 = E >> 2;
    const int4* d4 = (const int4*)edst;
    const int4* s4 = (const int4*)esrc;
    for (int j = sid; j < e4; j += ST) {
        int4 d = d4[j];
        unsigned h0 = (sh.bmp[(unsigned)d.x >> 5] >> (d.x & 31)) & 1u;
        unsigned h1 = (sh.bmp[(unsigned)d.y >> 5] >> (d.y & 31)) & 1u;
        unsigned h2 = (sh.bmp[(unsigned)d.z >> 5] >> (d.z & 31)) & 1u;
        unsigned h3 = (sh.bmp[(unsigned)d.w >> 5] >> (d.w & 31)) & 1u;
        if (h0 | h1 | h2 | h3) {
            int4 s = s4[j];
            if (h0) applyOne(s.x, d.x);
            if (h1) applyOne(s.y, d.y);
            if (h2) applyOne(s.z, d.z);
            if (h3) applyOne(s.w, d.w);
        }
    }
    if (sid == 0) {
        for (int e = e4 << 2; e < E; ++e) {
            int d = edst[e];
            if ((g_bitmap[(unsigned)d >> 5] >> (d & 31)) & 1u) applyOne(esrc[e], d);
        }
    }
}

// warp computes norm + 8 class dots for a 256-float row vs smem hx
// lane 0 gets results in dots[0..7], *den
__device__ __forceinline__ void warpScore(const float* __restrict__ esrow,
                                          const float* hxs, float* dots, float* den) {
    int lane = threadIdx.x & 31;
    const float4* r4 = (const float4*)(esrow + lane * 8);
    float4 a = r4[0], b = r4[1];
    float x[8] = {a.x, a.y, a.z, a.w, b.x, b.y, b.z, b.w};
    float acc[9];
    #pragma unroll
    for (int k = 0; k < 9; k++) acc[k] = 0.f;
    #pragma unroll
    for (int k = 0; k < 8; k++) acc[8] += x[k] * x[k];
    #pragma unroll
    for (int c = 0; c < NC; c++) {
        const float* h = hxs + c * F + lane * 8;
        #pragma unroll
        for (int k = 0; k < 8; k++) acc[c] += x[k] * h[k];
    }
    #pragma unroll
    for (int o = 16; o; o >>= 1) {
        #pragma unroll
        for (int k = 0; k < 9; k++)
            acc[k] += __shfl_down_sync(0xffffffffu, acc[k], o);
    }
    #pragma unroll
    for (int c = 0; c < NC; c++) dots[c] = acc[c];
    *den = sqrtf(acc[8]) + EPSF;
}

__global__ __launch_bounds__(NT, 1) void fused_kernel(
    const int* __restrict__ seeds, const int* __restrict__ esrc,
    const int* __restrict__ edst, const float* __restrict__ es,
    const float* __restrict__ W_ih, const float* __restrict__ W_hh,
    const float* __restrict__ b_ih, const float* __restrict__ b_hh,
    float* __restrict__ out, int E, int n)
{
    __shared__ SH sh;
    __shared__ float redsm[NWARP];
    __shared__ unsigned sBase;
    const int NB = gridDim.x;
    const int tid = threadIdx.x, bid = blockIdx.x;
    const int gid = bid * NT + tid, GT = NB * NT;
    const int wid = tid >> 5, lane = tid & 31;

    if (tid == 0) sBase = *(volatile unsigned*)&g_barGen;
    __syncthreads();
    const unsigned barBase = sBase;
    unsigned nbar = 0;

    // ---- P0: zero state ----
    for (int i = gid; i < 2 * n; i += GT) g_counts[i] = 0u;
    for (int i = gid; i < n; i += GT) {
        g_entity[i] = 0; g_cg[i] = 0u; g_newMask[i] = 0u;
    }
    for (int i = gid; i < BMPW; i += GT) g_bitmap[i] = 0u;
    for (int i = gid; i < NC * F; i += GT) g_hx[i] = 0.f;
    if (gid == 0) g_candCount = 0;
    gsync(barBase, nbar, NB);

    // ---- P1: seed marks + pool from seeds ----
    if (bid == 0 && tid < NC * SC) {
        int s = seeds[tid], c = tid >> 4;
        g_entity[s] = 1;
        atomicOr(&g_cg[s], 1u << c);
        atomicOr(&g_newMask[s], 1u << c);
        atomicOr(&g_bitmap[(unsigned)s >> 5], 1u << (s & 31));
        g_markNode[tid] = s;
    }
    if (bid >= 1 && bid <= NC && tid < F) {
        int c = bid - 1;
        float s = 0.f;
        #pragma unroll
        for (int j = 0; j < SC; j++)
            s += es[(size_t)seeds[c * SC + j] * F + tid];
        g_inp[c * F + tid] = s * (1.0f / SC);
    }
    gsync(barBase, nbar, NB);

    for (int step = 0; step < NSTEP; step++) {
        int mm = (step == 0) ? 3 : 2;

        // ---- A: gemm (blocks < GEMMB)  ||  edge scan (blocks >= GEMMB) ----
        if (gid == 0) g_candCount = 0;
        if (bid < GEMMB) {
            for (int i = tid; i < NC * F; i += NT) {
                sh.shv[i] = g_inp[i];
                sh.shv[NC * F + i] = g_hx[i];
            }
            __syncthreads();
            int warp = bid * NWARP + wid;
            int totalW = GEMMB * NWARP;
            for (int job = warp; job < 2 * 3 * F; job += totalW) {
                int m = (job >= 3 * F) ? 1 : 0;
                int r = job - m * 3 * F;
                const float4* w4 = (const float4*)((m ? W_hh : W_ih) + (size_t)r * F);
                float4 a = w4[lane * 2], b = w4[lane * 2 + 1];
                float wv[8] = {a.x, a.y, a.z, a.w, b.x, b.y, b.z, b.w};
                const float* vecb = sh.shv + m * NC * F;
                #pragma unroll
                for (int c = 0; c < NC; c++) {
                    const float* v = vecb + c * F + lane * 8;
                    float d = wv[0]*v[0] + wv[1]*v[1] + wv[2]*v[2] + wv[3]*v[3]
                            + wv[4]*v[4] + wv[5]*v[5] + wv[6]*v[6] + wv[7]*v[7];
                    #pragma unroll
                    for (int o = 16; o; o >>= 1) d += __shfl_down_sync(0xffffffffu, d, o);
                    if (lane == 0) (m ? g_gh : g_gi)[c * 3 * F + r] = d;
                }
            }
        } else {
            edgeScan(sh, esrc, edst, E, bid, NB);
        }
        gsync(barBase, nbar, NB);

        // ---- B: gate (blocks 0-7)  ||  valid scan + clears (blocks 8+) ----
        if (bid < NC) {
            int c = bid;
            float h = 0.f;
            if (tid < F) {
                int k = tid;
                float gir = g_gi[c*3*F + k]       + b_ih[k];
                float giz = g_gi[c*3*F + F + k]   + b_ih[F + k];
                float gin = g_gi[c*3*F + 2*F + k] + b_ih[2*F + k];
                float ghr = g_gh[c*3*F + k]       + b_hh[k];
                float ghz = g_gh[c*3*F + F + k]   + b_hh[F + k];
                float ghn = g_gh[c*3*F + 2*F + k] + b_hh[2*F + k];
                float r = 1.f / (1.f + expf(-(gir + ghr)));
                float z = 1.f / (1.f + expf(-(giz + ghz)));
                float nn = tanhf(gin + r * ghn);
                h = (1.f - z) * nn + z * g_hx[c * F + k];
                g_hx[c * F + k] = h;
                out[HX_OFF + step * NC * F + c * F + k] = h;
            }
            float s2 = blockSumAll(h * h, redsm);
            if (tid == 0) g_hxden[c] = sqrtf(s2) + EPSF;
        } else {
            if (bid == NC && tid < NC * SC) g_newMask[g_markNode[tid]] = 0u;
            int start = (bid - NC) * NT + tid, stride = (NB - NC) * NT;
            for (int i = start; i < BMPW; i += stride) g_bitmap[i] = 0u;
            for (int i = start; i < n; i += stride) {
                unsigned vm = 0;
                if (!g_entity[i]) {
                    uint2 u = *(const uint2*)&g_counts[(size_t)i * 2];
                    #pragma unroll
                    for (int c = 0; c < 4; c++)
                        if (((u.x >> (c * 8)) & 0xffu) >= (unsigned)mm) vm |= 1u << c;
                    #pragma unroll
                    for (int c = 0; c < 4; c++)
                        if (((u.y >> (c * 8)) & 0xffu) >= (unsigned)mm) vm |= 1u << (c + 4);
                }
                g_valid[i] = (unsigned char)vm;
                if (vm) {
                    int p = atomicAdd(&g_candCount, 1);
                    if (p < CANDCAP) g_cand[p] = i;
                }
            }
        }
        gsync(barBase, nbar, NB);

        // ---- C: score candidates (warp per candidate) ----
        {
            int cc = g_candCount; if (cc > CANDCAP) cc = CANDCAP;
            for (int i = tid; i < NC * F; i += NT) sh.hxsc[i] = g_hx[i];
            __syncthreads();
            int warpG = bid * NWARP + wid;
            for (int ci = warpG; ci < cc; ci += NB * NWARP) {
                int node = g_cand[ci];
                float dots[NC], den;
                warpScore(es + (size_t)node * F, sh.hxsc, dots, &den);
                if (lane == 0) {
                    #pragma unroll
                    for (int c = 0; c < NC; c++)
                        g_candScore[ci * NC + c] =
                            0.5f * (dots[c] / (den * g_hxden[c])) + 0.5f;
                }
            }
        }
        gsync(barBase, nbar, NB);

        // ---- D: select + finalize + pool (blocks 0-7, one per class) ----
        if (bid < NC) {
            int c = bid;
            int cc = g_candCount; if (cc > CANDCAP) cc = CANDCAP;
            for (int i = tid; i < NC * F; i += NT) sh.sel.hxs[i] = g_hx[i];
            for (int i = tid; i < CANDCAP / 32; i += NT) sh.sel.ch[i] = 0u;
            __syncthreads();
            int slot = 0;
            for (; slot < SC; ++slot) {
                unsigned long long best = 0ull;
                for (int j = tid; j < cc; j += NT) {
                    int nd = g_cand[j];
                    if (((g_valid[nd] >> c) & 1u) && !((sh.sel.ch[j >> 5] >> (j & 31)) & 1u)) {
                        unsigned u = __float_as_uint(g_candScore[j * NC + c]);
                        u ^= (u & 0x80000000u) ? 0xffffffffu : 0x80000000u;
                        unsigned long long k = (((unsigned long long)u) << 32)
                                             | (unsigned long long)(0xffffffffu - (unsigned)nd);
                        if (k > best) best = k;
                    }
                }
                #pragma unroll
                for (int o = 16; o; o >>= 1) {
                    unsigned long long v = __shfl_down_sync(0xffffffffu, best, o);
                    if (v > best) best = v;
                }
                if (lane == 0) sh.sel.red[wid] = best;
                __syncthreads();
                if (wid == 0) {
                    unsigned long long v = (lane < NWARP) ? sh.sel.red[lane] : 0ull;
                    #pragma unroll
                    for (int o = 8; o; o >>= 1) {
                        unsigned long long w = __shfl_down_sync(0xffffffffu, v, o);
                        if (w > v) v = w;
                    }
                    if (lane == 0) sh.sel.bestk = v;
                }
                __syncthreads();
                unsigned long long bk = sh.sel.bestk;
                if (bk == 0ull) break;
                int node = (int)(0xffffffffu - (unsigned)(bk & 0xffffffffu));
                for (int j = tid; j < cc; j += NT)
                    if (g_cand[j] == node) sh.sel.ch[j >> 5] |= (1u << (j & 31));
                if (tid == 0) {
                    sh.sel.snode[slot] = node;
                    out[SEL_OFF + step * NC * SC + c * SC + slot] = (float)node;
                }
                __syncthreads();
            }
            if (tid == 0) {
                int p = 0;
                for (; slot < SC; ++slot) {
                    while ((g_valid[p] >> c) & 1u) ++p;
                    sh.sel.snode[slot] = p;
                    out[SEL_OFF + step * NC * SC + c * SC + slot] = (float)p;
                    ++p;
                }
                out[STEP_OFF + step * NC + c] = 16.0f;
            }
            __syncthreads();
            // marks
            if (tid < SC) {
                int node = sh.sel.snode[tid];
                unsigned old = atomicOr(&g_cg[node], 1u << c);
                g_entity[node] = 1;
                g_markNode[c * SC + tid] = node;
                if (!((old >> c) & 1u)) {
                    atomicOr(&g_newMask[node], 1u << c);
                    atomicOr(&g_bitmap[(unsigned)node >> 5], 1u << (node & 31));
                }
            }
            // output rows: warp j -> slot j
            {
                int node = sh.sel.snode[wid];
                unsigned vm = g_valid[node];
                float* orow = out + OUT_OFF + step * (NC * SC * NC) + (c * SC + wid) * NC;
                if (vm == 0u) {
                    if (lane < NC) orow[lane] = 0.f;
                } else {
                    float dots[NC], den;
                    warpScore(es + (size_t)node * F, sh.sel.hxs, dots, &den);
                    if (lane == 0) {
                        #pragma unroll
                        for (int c2 = 0; c2 < NC; c2++)
                            orow[c2] = 0.5f * (dots[c2] / (den * g_hxden[c2])) + 0.5f;
                    }
                }
            }
            __syncthreads();
            // pool for next step
            if (step < NSTEP - 1 && tid < F) {
                float s = 0.f;
                #pragma unroll
                for (int j = 0; j < SC; j++)
                    s += es[(size_t)sh.sel.snode[j] * F + tid];
                g_inp[c * F + tid] = s * (1.0f / SC);
            }
        }
        gsync(barBase, nbar, NB);
    }
}

// ---------------- launch ----------------
extern "C" void kernel_launch(void* const* d_in, const int* in_sizes, int n_in,
                              void* d_out, int out_size) {
    const int*   seeds = (const int*)d_in[0];
    const int*   esrc  = (const int*)d_in[1];
    const int*   edst  = (const int*)d_in[2];
    const float* es    = (const float*)d_in[3];
    const float* W_ih  = (const float*)d_in[4];
    const float* W_hh  = (const float*)d_in[5];
    const float* b_ih  = (const float*)d_in[6];
    const float* b_hh  = (const float*)d_in[7];
    float* out = (float*)d_out;
    int E = in_sizes[1];
    int n = in_sizes[3] / F;

    int dev = 0, nsm = 0;
    cudaGetDevice(&dev);
    cudaDeviceGetAttribute(&nsm, cudaDevAttrMultiProcessorCount, dev);
    if (nsm <= 0 || nsm > 512) nsm = 148;

    fused_kernel<<<nsm, NT>>>(seeds, esrc, edst, es, W_ih, W_hh, b_ih, b_hh, out, E, n);
}